// round 5
// baseline (speedup 1.0000x reference)
#include <cuda_runtime.h>
#include <cuda_bf16.h>
#include <cstdint>

#define N_ROWS 16384
#define DIM 128
#define SQRT_SCALE2 4.5398160f   // sqrt(log2(e)/0.07)
#define GRID 148
#define NUNITS 8256              // 128*129/2 upper-triangular block pairs

__device__ __nv_bfloat16 g_fn[N_ROWS * DIM];
__device__ float g_partial[GRID * N_ROWS];
__device__ float g_blocksum[64];

#define TILE_BYTES 34816                 // 128 rows x 272B
#define SM_ROWACC  (4 * TILE_BYTES)      // 16384 floats
#define SM_RED     (SM_ROWACC + 65536)
#define SM_CRED    (SM_RED + 2048)
#define SMEM_TOTAL 208896

__device__ __forceinline__ float fast_ex2(float x) {
    float y; asm("ex2.approx.ftz.f32 %0, %1;" : "=f"(y) : "f"(x)); return y;
}
__device__ __forceinline__ uint32_t smem_u32(const void* p) {
    uint32_t a;
    asm("{ .reg .u64 t; cvta.to.shared.u64 t, %1; cvt.u32.u64 %0, t; }" : "=r"(a) : "l"(p));
    return a;
}
__device__ __forceinline__ void cp16(uint32_t dst, const void* src) {
    asm volatile("cp.async.cg.shared.global [%0], [%1], 16;" :: "r"(dst), "l"(src));
}
__device__ __forceinline__ void cp_commit()   { asm volatile("cp.async.commit_group;"); }
__device__ __forceinline__ void cp_wait_all() { asm volatile("cp.async.wait_group 0;" ::: "memory"); }

__device__ __forceinline__ void ldsm4(uint32_t r[4], uint32_t addr) {
    asm volatile("ldmatrix.sync.aligned.m8n8.x4.shared.b16 {%0,%1,%2,%3}, [%4];"
                 : "=r"(r[0]), "=r"(r[1]), "=r"(r[2]), "=r"(r[3]) : "r"(addr));
}
__device__ __forceinline__ void mma16816(float* c, const uint32_t a[4], const uint32_t* b) {
    asm volatile(
      "mma.sync.aligned.m16n8k16.row.col.f32.bf16.bf16.f32 "
      "{%0,%1,%2,%3}, {%4,%5,%6,%7}, {%8,%9}, {%0,%1,%2,%3};\n"
      : "+f"(c[0]), "+f"(c[1]), "+f"(c[2]), "+f"(c[3])
      : "r"(a[0]), "r"(a[1]), "r"(a[2]), "r"(a[3]), "r"(b[0]), "r"(b[1]));
}

__device__ __forceinline__ int tri_base(int bi) { return bi * 128 - (bi * (bi - 1)) / 2; }
__device__ __forceinline__ void decode_unit(int u, int& bi, int& bj) {
    int b = (int)((257.0f - sqrtf(66049.0f - 8.0f * (float)u)) * 0.5f);
    while (tri_base(b + 1) <= u) b++;
    while (tri_base(b) > u) b--;
    bi = b;
    bj = b + (u - tri_base(b));
}

__device__ __forceinline__ void load_tile(uint32_t dstbase, const __nv_bfloat16* src, int tid) {
    #pragma unroll
    for (int i = 0; i < 4; i++) {
        int c = tid + 512 * i;
        int row = c >> 4, q = c & 15;
        cp16(dstbase + (uint32_t)(row * 17 + q) * 16, src + row * DIM + q * 8);
    }
}

// ---------------- Kernel 1: normalize + prescale ----------------
__global__ void __launch_bounds__(256) normalize_kernel(const float* __restrict__ feats) {
    int warp = threadIdx.x >> 5, lane = threadIdx.x & 31;
    int row  = blockIdx.x * 8 + warp;
    const float4* src = reinterpret_cast<const float4*>(feats + (size_t)row * DIM);
    float4 v = src[lane];
    float ss = v.x*v.x + v.y*v.y + v.z*v.z + v.w*v.w;
    #pragma unroll
    for (int o = 16; o; o >>= 1) ss += __shfl_xor_sync(0xffffffffu, ss, o);
    float inv = SQRT_SCALE2 / fmaxf(sqrtf(ss), 1e-8f);
    __nv_bfloat162 p0 = __floats2bfloat162_rn(v.x*inv, v.y*inv);
    __nv_bfloat162 p1 = __floats2bfloat162_rn(v.z*inv, v.w*inv);
    uint2 w;
    w.x = *reinterpret_cast<uint32_t*>(&p0);
    w.y = *reinterpret_cast<uint32_t*>(&p1);
    reinterpret_cast<uint2*>(g_fn + (size_t)row * DIM)[lane] = w;
}

// ---------------- Kernel 2: symmetric GEMM + pipelined exp epilogue ----------------
struct Ctx {
    uint32_t sbase;
    uint32_t aOff0, aOff1, bOff0, bOff1;
    float* rowacc; float* red; float* cred;
    int tid, wm, wn, g, t, epi_r0, epi_c0;
};

// One pipeline step: MMA(unit u, tiles in `buf`) into cc, interleaved exp of
// previous unit's accumulators cp; then flush previous unit's row/col partials.
template<bool EPI>
__device__ __forceinline__ void step(const Ctx& cx, int u, int buf,
                                     int pbi, int pbj,
                                     float (&cc)[32], float (&cp)[32]) {
    const int un = u + GRID;
    const bool has_next = (un < NUNITS);

    cp_wait_all();
    __syncthreads();              // tiles[buf] ready; prior red/cred reads done

    if (has_next) {
        int nbi, nbj;
        decode_unit(un, nbi, nbj);
        uint32_t nb = cx.sbase + (uint32_t)(buf ^ 1) * (2 * TILE_BYTES);
        load_tile(nb,              g_fn + (size_t)nbi * 16384, cx.tid);
        load_tile(nb + TILE_BYTES, g_fn + (size_t)nbj * 16384, cx.tid);
        cp_commit();
    }

    const uint32_t abase = cx.sbase + (uint32_t)buf * (2 * TILE_BYTES);
    const uint32_t bbase = abase + TILE_BYTES;
    const bool diag_prev = EPI && (pbi == pbj);

    #pragma unroll
    for (int e = 0; e < 32; e++) cc[e] = 0.f;
    float rr[4] = {0.f, 0.f, 0.f, 0.f};
    float ca[8] = {0.f, 0.f, 0.f, 0.f, 0.f, 0.f, 0.f, 0.f};

    #pragma unroll
    for (int ks = 0; ks < 8; ks++) {
        uint32_t a0[4], a1[4], b0[4], b1[4];
        ldsm4(a0, abase + cx.aOff0 + ks * 32);
        ldsm4(a1, abase + cx.aOff1 + ks * 32);
        ldsm4(b0, bbase + cx.bOff0 + ks * 32);
        ldsm4(b1, bbase + cx.bOff1 + ks * 32);
        mma16816(&cc[0],  a0, b0 + 0); mma16816(&cc[4],  a0, b0 + 2);
        mma16816(&cc[8],  a0, b1 + 0); mma16816(&cc[12], a0, b1 + 2);
        mma16816(&cc[16], a1, b0 + 0); mma16816(&cc[20], a1, b0 + 2);
        mma16816(&cc[24], a1, b1 + 0); mma16816(&cc[28], a1, b1 + 2);
        if (EPI) {
            #pragma unroll
            for (int i = 0; i < 4; i++) {
                const int e = ks * 4 + i;
                const int mt = e >> 4, nt = (e >> 2) & 3, comp = e & 3;
                float ex = fast_ex2(cp[e]);
                int r  = cx.epi_r0 + mt * 16 + (comp & 2) * 4;
                int cl = cx.epi_c0 + nt * 8 + (comp & 1);
                if (diag_prev && r == cl) ex = 1.f;    // masked diag: exp==1
                rr[mt * 2 + (comp >> 1)] += ex;
                ca[nt * 2 + (comp & 1)] += ex;
            }
        }
    }

    if (EPI) {
        // row partials: reduce over t (4 lanes per row)
        #pragma unroll
        for (int i = 0; i < 4; i++) {
            rr[i] += __shfl_xor_sync(0xffffffffu, rr[i], 1);
            rr[i] += __shfl_xor_sync(0xffffffffu, rr[i], 2);
        }
        if (cx.t == 0) {
            #pragma unroll
            for (int i = 0; i < 4; i++) {
                int r = cx.wm * 32 + (i >> 1) * 16 + cx.g + (i & 1) * 8;
                cx.red[r * 4 + cx.wn] = rr[i];
            }
        }
        if (!diag_prev) {
            // col partials: reduce over g
            #pragma unroll
            for (int i = 0; i < 8; i++) {
                ca[i] += __shfl_xor_sync(0xffffffffu, ca[i], 4);
                ca[i] += __shfl_xor_sync(0xffffffffu, ca[i], 8);
                ca[i] += __shfl_xor_sync(0xffffffffu, ca[i], 16);
            }
            if ((cx.tid & 31) < 4) {
                #pragma unroll
                for (int i = 0; i < 8; i++) {
                    int cl = cx.wn * 32 + (i >> 1) * 8 + 2 * cx.t + (i & 1);
                    cx.cred[cl * 4 + cx.wm] = ca[i];
                }
            }
        }
        __syncthreads();
        if (cx.tid < 128) {
            float4 v = reinterpret_cast<const float4*>(cx.red)[cx.tid];
            cx.rowacc[pbi * 128 + cx.tid] += (v.x + v.y) + (v.z + v.w);
        } else if (cx.tid < 256 && !diag_prev) {
            int c2 = cx.tid - 128;
            float4 v = reinterpret_cast<const float4*>(cx.cred)[c2];
            cx.rowacc[pbj * 128 + c2] += (v.x + v.y) + (v.z + v.w);
        }
    }
}

__device__ __forceinline__ void tail_epi(const Ctx& cx, int pbi, int pbj, float (&cp)[32]) {
    const bool diag = (pbi == pbj);
    float rr[4] = {0.f, 0.f, 0.f, 0.f};
    float ca[8] = {0.f, 0.f, 0.f, 0.f, 0.f, 0.f, 0.f, 0.f};
    #pragma unroll
    for (int e = 0; e < 32; e++) {
        const int mt = e >> 4, nt = (e >> 2) & 3, comp = e & 3;
        float ex = fast_ex2(cp[e]);
        int r  = cx.epi_r0 + mt * 16 + (comp & 2) * 4;
        int cl = cx.epi_c0 + nt * 8 + (comp & 1);
        if (diag && r == cl) ex = 1.f;
        rr[mt * 2 + (comp >> 1)] += ex;
        ca[nt * 2 + (comp & 1)] += ex;
    }
    #pragma unroll
    for (int i = 0; i < 4; i++) {
        rr[i] += __shfl_xor_sync(0xffffffffu, rr[i], 1);
        rr[i] += __shfl_xor_sync(0xffffffffu, rr[i], 2);
    }
    if (cx.t == 0) {
        #pragma unroll
        for (int i = 0; i < 4; i++) {
            int r = cx.wm * 32 + (i >> 1) * 16 + cx.g + (i & 1) * 8;
            cx.red[r * 4 + cx.wn] = rr[i];
        }
    }
    if (!diag) {
        #pragma unroll
        for (int i = 0; i < 8; i++) {
            ca[i] += __shfl_xor_sync(0xffffffffu, ca[i], 4);
            ca[i] += __shfl_xor_sync(0xffffffffu, ca[i], 8);
            ca[i] += __shfl_xor_sync(0xffffffffu, ca[i], 16);
        }
        if ((cx.tid & 31) < 4) {
            #pragma unroll
            for (int i = 0; i < 8; i++) {
                int cl = cx.wn * 32 + (i >> 1) * 8 + 2 * cx.t + (i & 1);
                cx.cred[cl * 4 + cx.wm] = ca[i];
            }
        }
    }
    __syncthreads();
    if (cx.tid < 128) {
        float4 v = reinterpret_cast<const float4*>(cx.red)[cx.tid];
        cx.rowacc[pbi * 128 + cx.tid] += (v.x + v.y) + (v.z + v.w);
    } else if (cx.tid < 256 && !diag) {
        int c2 = cx.tid - 128;
        float4 v = reinterpret_cast<const float4*>(cx.cred)[c2];
        cx.rowacc[pbj * 128 + c2] += (v.x + v.y) + (v.z + v.w);
    }
}

__global__ void __launch_bounds__(512, 1) simclr_sym_kernel() {
    extern __shared__ unsigned char smem_raw[];
    Ctx cx;
    cx.sbase  = smem_u32(smem_raw);
    cx.rowacc = reinterpret_cast<float*>(smem_raw + SM_ROWACC);
    cx.red    = reinterpret_cast<float*>(smem_raw + SM_RED);
    cx.cred   = reinterpret_cast<float*>(smem_raw + SM_CRED);
    cx.tid = threadIdx.x;
    const int warp = cx.tid >> 5, lane = cx.tid & 31;
    cx.g = lane >> 2; cx.t = lane & 3;
    cx.wm = warp >> 2; cx.wn = warp & 3;
    cx.epi_r0 = cx.wm * 32 + cx.g;
    cx.epi_c0 = cx.wn * 32 + 2 * cx.t;
    {
        int rowA = lane & 15, koffA = (lane >> 4) * 16;
        cx.aOff0 = (uint32_t)((cx.wm * 32 + 0  + rowA) * 272 + koffA);
        cx.aOff1 = (uint32_t)((cx.wm * 32 + 16 + rowA) * 272 + koffA);
        int rowB = ((lane & 16) >> 1) + (lane & 7), koffB = ((lane >> 3) & 1) * 16;
        cx.bOff0 = (uint32_t)((cx.wn * 32 + 0  + rowB) * 272 + koffB);
        cx.bOff1 = (uint32_t)((cx.wn * 32 + 16 + rowB) * 272 + koffB);
    }

    #pragma unroll
    for (int i = 0; i < 8; i++)
        reinterpret_cast<float4*>(cx.rowacc)[cx.tid + 512 * i] = make_float4(0.f, 0.f, 0.f, 0.f);

    int u = blockIdx.x;
    int bi, bj;
    decode_unit(u, bi, bj);
    load_tile(cx.sbase,              g_fn + (size_t)bi * 16384, cx.tid);
    load_tile(cx.sbase + TILE_BYTES, g_fn + (size_t)bj * 16384, cx.tid);
    cp_commit();

    float c0[32], c1[32];
    step<false>(cx, u, 0, 0, 0, c0, c1);      // MMA(u0) into c0
    int pbi = bi, pbj = bj;
    u += GRID;
    int buf = 1;
    bool ping = true;                          // true: cc=c1 (prev in c0)
    #pragma unroll 1
    while (u < NUNITS) {
        decode_unit(u, bi, bj);
        if (ping) step<true>(cx, u, buf, pbi, pbj, c1, c0);
        else      step<true>(cx, u, buf, pbi, pbj, c0, c1);
        ping = !ping;
        pbi = bi; pbj = bj;
        u += GRID; buf ^= 1;
    }
    __syncthreads();                           // red/cred settle before tail reuse
    if (ping) tail_epi(cx, pbi, pbj, c0);
    else      tail_epi(cx, pbi, pbj, c1);

    __syncthreads();
    float* dst = g_partial + (size_t)blockIdx.x * N_ROWS;
    #pragma unroll
    for (int i = 0; i < 8; i++) {
        int idx = cx.tid + 512 * i;
        reinterpret_cast<float4*>(dst)[idx] = reinterpret_cast<const float4*>(cx.rowacc)[idx];
    }
}

// ---------------- Kernel 3: row sums over partials + log + block-sum ----------------
__global__ void __launch_bounds__(256) lse_kernel() {
    __shared__ float s[256];
    int row = blockIdx.x * 256 + threadIdx.x;
    float s0 = 0.f, s1 = 0.f, s2 = 0.f, s3 = 0.f;
    #pragma unroll 4
    for (int c = 0; c < GRID; c += 4) {
        s0 += g_partial[(size_t)c * N_ROWS + row];
        s1 += g_partial[(size_t)(c + 1) * N_ROWS + row];
        s2 += g_partial[(size_t)(c + 2) * N_ROWS + row];
        s3 += g_partial[(size_t)(c + 3) * N_ROWS + row];
    }
    float l = logf((s0 + s1) + (s2 + s3));
    s[threadIdx.x] = l;
    __syncthreads();
    #pragma unroll
    for (int o = 128; o; o >>= 1) {
        if (threadIdx.x < o) s[threadIdx.x] += s[threadIdx.x + o];
        __syncthreads();
    }
    if (threadIdx.x == 0) g_blocksum[blockIdx.x] = s[0];
}

// ---------------- Kernel 4: mean - pos ----------------
__global__ void __launch_bounds__(64) final_reduce(float* __restrict__ out) {
    float v = g_blocksum[threadIdx.x];
    #pragma unroll
    for (int o = 16; o; o >>= 1) v += __shfl_xor_sync(0xffffffffu, v, o);
    __shared__ float w[2];
    if ((threadIdx.x & 31) == 0) w[threadIdx.x >> 5] = v;
    __syncthreads();
    if (threadIdx.x == 0)
        out[0] = (w[0] + w[1]) * (1.0f / 16384.0f) - 1.2857142857142857e-13f;
}

extern "C" void kernel_launch(void* const* d_in, const int* in_sizes, int n_in,
                              void* d_out, int out_size) {
    const float* feats = (const float*)d_in[0];
    float* out = (float*)d_out;

    cudaFuncSetAttribute(simclr_sym_kernel,
                         cudaFuncAttributeMaxDynamicSharedMemorySize, SMEM_TOTAL);

    normalize_kernel<<<N_ROWS / 8, 256>>>(feats);
    simclr_sym_kernel<<<GRID, 512, SMEM_TOTAL>>>();
    lse_kernel<<<64, 256>>>();
    final_reduce<<<1, 64>>>(out);
}

// round 6
// speedup vs baseline: 1.1967x; 1.1967x over previous
#include <cuda_runtime.h>
#include <cuda_bf16.h>
#include <cstdint>

#define N_ROWS 16384
#define DIM 128
#define SQRT_SCALE2 4.5398160f   // sqrt(log2(e)/0.07)
#define GRID 148
#define NUNITS 8256              // 128*129/2 upper-triangular block pairs

__device__ __nv_bfloat16 g_fn[N_ROWS * DIM];
__device__ float g_partial[GRID * N_ROWS];
__device__ float g_blocksum[64];
__device__ unsigned int g_ctr0;   // grid barrier (normalize -> gemm), monotonic
__device__ unsigned int g_ctr2;   // lse -> final fusion counter, monotonic

#define TILE_BYTES 34816                 // 128 rows x 272B (136 bf16 padded)
#define SM_ROWACC  (4 * TILE_BYTES)      // 139264 : 16384 floats (64KB)
#define SM_RED     (SM_ROWACC + 65536)   // 204800 : 2 parities x 128x4 floats
#define SM_CRED    (SM_RED + 4096)       // 208896 : 2 parities x 128x4 floats
#define SMEM_TOTAL (SM_CRED + 4096)      // 212992

__device__ __forceinline__ float fast_ex2(float x) {
    float y; asm("ex2.approx.ftz.f32 %0, %1;" : "=f"(y) : "f"(x)); return y;
}
__device__ __forceinline__ uint32_t smem_u32(const void* p) {
    uint32_t a;
    asm("{ .reg .u64 t; cvta.to.shared.u64 t, %1; cvt.u32.u64 %0, t; }" : "=r"(a) : "l"(p));
    return a;
}
__device__ __forceinline__ void cp16(uint32_t dst, const void* src) {
    asm volatile("cp.async.cg.shared.global [%0], [%1], 16;" :: "r"(dst), "l"(src));
}
__device__ __forceinline__ void cp_commit()   { asm volatile("cp.async.commit_group;"); }
__device__ __forceinline__ void cp_wait_all() { asm volatile("cp.async.wait_group 0;" ::: "memory"); }

__device__ __forceinline__ void ldsm4(uint32_t r[4], uint32_t addr) {
    asm volatile("ldmatrix.sync.aligned.m8n8.x4.shared.b16 {%0,%1,%2,%3}, [%4];"
                 : "=r"(r[0]), "=r"(r[1]), "=r"(r[2]), "=r"(r[3]) : "r"(addr));
}
__device__ __forceinline__ void mma16816(float* c, const uint32_t a[4], const uint32_t* b) {
    asm volatile(
      "mma.sync.aligned.m16n8k16.row.col.f32.bf16.bf16.f32 "
      "{%0,%1,%2,%3}, {%4,%5,%6,%7}, {%8,%9}, {%0,%1,%2,%3};\n"
      : "+f"(c[0]), "+f"(c[1]), "+f"(c[2]), "+f"(c[3])
      : "r"(a[0]), "r"(a[1]), "r"(a[2]), "r"(a[3]), "r"(b[0]), "r"(b[1]));
}

__device__ __forceinline__ int tri_base(int bi) { return bi * 128 - (bi * (bi - 1)) / 2; }
__device__ __forceinline__ void decode_unit(int u, int& bi, int& bj) {
    int b = (int)((257.0f - sqrtf(66049.0f - 8.0f * (float)u)) * 0.5f);
    while (tri_base(b + 1) <= u) b++;
    while (tri_base(b) > u) b--;
    bi = b;
    bj = b + (u - tri_base(b));
}

__device__ __forceinline__ void load_tile(uint32_t dstbase, const __nv_bfloat16* src, int tid) {
    #pragma unroll
    for (int i = 0; i < 4; i++) {
        int c = tid + 512 * i;
        int row = c >> 4, q = c & 15;
        cp16(dstbase + (uint32_t)(row * 17 + q) * 16, src + row * DIM + q * 8);
    }
}

// One pipeline step: MMA of current unit into cc, interleaved ex2 of prev
// unit's accumulators cp; flush prev epilogue to red/cred[wp]; accumulate
// unit u-2 (pp blocks) from red/cred[wp^1] into rowacc.
template<bool EPI>
__device__ __forceinline__ void step(uint32_t sbase, unsigned char* smem_raw,
                                     int abuf, int bbuf,
                                     bool has_next, bool loadA_next, int nbi, int nbj,
                                     bool pdiag, int ppbi, int ppbj, bool ppdiag, int wp,
                                     float (&cc)[32], float (&cp)[32]) {
    const int tid = threadIdx.x;
    const int warp = tid >> 5, lane = tid & 31;
    const int g = lane >> 2, t = lane & 3;
    const int wm = warp >> 2, wn = warp & 3;

    cp_wait_all();
    __syncthreads();   // tiles ready; prior red/cred writes visible

    if (has_next) {
        load_tile(sbase + (uint32_t)(2 + (bbuf ^ 1)) * TILE_BYTES,
                  g_fn + (size_t)nbj * 16384, tid);
        if (loadA_next)
            load_tile(sbase + (uint32_t)(abuf ^ 1) * TILE_BYTES,
                      g_fn + (size_t)nbi * 16384, tid);
        cp_commit();
    }

    const uint32_t abase = sbase + (uint32_t)abuf * TILE_BYTES;
    const uint32_t bbase = sbase + (uint32_t)(2 + bbuf) * TILE_BYTES;
    uint32_t aA0, aA1, aB0, aB1;
    {
        int rowA = lane & 15, koffA = (lane >> 4) * 16;
        aA0 = abase + (uint32_t)((wm * 32 + rowA) * 272 + koffA);
        aA1 = aA0 + 16 * 272;
        int rowB = ((lane & 16) >> 1) + (lane & 7), koffB = ((lane >> 3) & 1) * 16;
        aB0 = bbase + (uint32_t)((wn * 32 + rowB) * 272 + koffB);
        aB1 = aB0 + 16 * 272;
    }
    const int epi_r0 = wm * 32 + g, epi_c0 = wn * 32 + 2 * t;

    #pragma unroll
    for (int e = 0; e < 32; e++) cc[e] = 0.f;
    float rr[4] = {0.f, 0.f, 0.f, 0.f};
    float ca[8] = {0.f, 0.f, 0.f, 0.f, 0.f, 0.f, 0.f, 0.f};

    #pragma unroll
    for (int ks = 0; ks < 8; ks++) {
        uint32_t a0[4], a1[4], b0[4], b1[4];
        ldsm4(a0, aA0 + ks * 32);
        ldsm4(a1, aA1 + ks * 32);
        ldsm4(b0, aB0 + ks * 32);
        ldsm4(b1, aB1 + ks * 32);
        mma16816(&cc[0],  a0, b0 + 0); mma16816(&cc[4],  a0, b0 + 2);
        mma16816(&cc[8],  a0, b1 + 0); mma16816(&cc[12], a0, b1 + 2);
        mma16816(&cc[16], a1, b0 + 0); mma16816(&cc[20], a1, b0 + 2);
        mma16816(&cc[24], a1, b1 + 0); mma16816(&cc[28], a1, b1 + 2);
        if (EPI) {
            #pragma unroll
            for (int i = 0; i < 4; i++) {
                const int e = ks * 4 + i;
                const int mt = e >> 4, nt = (e >> 2) & 3, comp = e & 3;
                float ex = fast_ex2(cp[e]);
                int r  = epi_r0 + mt * 16 + (comp & 2) * 4;
                int cl = epi_c0 + nt * 8 + (comp & 1);
                if (pdiag && r == cl) ex = 1.f;        // masked diag: exp==1
                rr[mt * 2 + (comp >> 1)] += ex;
                ca[nt * 2 + (comp & 1)] += ex;         // discarded for diag units
            }
        }
    }

    if (EPI) {
        #pragma unroll
        for (int i = 0; i < 4; i++) {
            rr[i] += __shfl_xor_sync(0xffffffffu, rr[i], 1);
            rr[i] += __shfl_xor_sync(0xffffffffu, rr[i], 2);
        }
        float* red  = (float*)(smem_raw + SM_RED  + wp * 2048);
        float* cred = (float*)(smem_raw + SM_CRED + wp * 2048);
        if (t == 0) {
            #pragma unroll
            for (int i = 0; i < 4; i++) {
                int r = wm * 32 + (i >> 1) * 16 + g + (i & 1) * 8;
                red[r * 4 + wn] = rr[i];
            }
        }
        if (!pdiag) {
            #pragma unroll
            for (int i = 0; i < 8; i++) {
                ca[i] += __shfl_xor_sync(0xffffffffu, ca[i], 4);
                ca[i] += __shfl_xor_sync(0xffffffffu, ca[i], 8);
                ca[i] += __shfl_xor_sync(0xffffffffu, ca[i], 16);
            }
            if (lane < 4) {
                #pragma unroll
                for (int i = 0; i < 8; i++) {
                    int cl = wn * 32 + (i >> 1) * 8 + 2 * t + (i & 1);
                    cred[cl * 4 + wm] = ca[i];
                }
            }
        }
        // accumulate unit u-2 from the other parity (written last step)
        float* rowacc = (float*)(smem_raw + SM_ROWACC);
        if (tid < 128) {
            const float4* rp = (const float4*)(smem_raw + SM_RED + (wp ^ 1) * 2048);
            float4 v = rp[tid];
            rowacc[ppbi * 128 + tid] += (v.x + v.y) + (v.z + v.w);
        } else if (tid < 256 && !ppdiag) {
            const float4* cp2 = (const float4*)(smem_raw + SM_CRED + (wp ^ 1) * 2048);
            float4 v = cp2[tid - 128];
            rowacc[ppbj * 128 + (tid - 128)] += (v.x + v.y) + (v.z + v.w);
        }
    }
}

__device__ __forceinline__ void tail_flush(unsigned char* smem_raw, float (&cp)[32],
                                           bool diag, int wp) {
    const int tid = threadIdx.x;
    const int warp = tid >> 5, lane = tid & 31;
    const int g = lane >> 2, t = lane & 3;
    const int wm = warp >> 2, wn = warp & 3;
    const int epi_r0 = wm * 32 + g, epi_c0 = wn * 32 + 2 * t;
    float rr[4] = {0.f, 0.f, 0.f, 0.f};
    float ca[8] = {0.f, 0.f, 0.f, 0.f, 0.f, 0.f, 0.f, 0.f};
    #pragma unroll
    for (int e = 0; e < 32; e++) {
        const int mt = e >> 4, nt = (e >> 2) & 3, comp = e & 3;
        float ex = fast_ex2(cp[e]);
        int r  = epi_r0 + mt * 16 + (comp & 2) * 4;
        int cl = epi_c0 + nt * 8 + (comp & 1);
        if (diag && r == cl) ex = 1.f;
        rr[mt * 2 + (comp >> 1)] += ex;
        ca[nt * 2 + (comp & 1)] += ex;
    }
    #pragma unroll
    for (int i = 0; i < 4; i++) {
        rr[i] += __shfl_xor_sync(0xffffffffu, rr[i], 1);
        rr[i] += __shfl_xor_sync(0xffffffffu, rr[i], 2);
    }
    float* red  = (float*)(smem_raw + SM_RED  + wp * 2048);
    float* cred = (float*)(smem_raw + SM_CRED + wp * 2048);
    if (t == 0) {
        #pragma unroll
        for (int i = 0; i < 4; i++) {
            int r = wm * 32 + (i >> 1) * 16 + g + (i & 1) * 8;
            red[r * 4 + wn] = rr[i];
        }
    }
    if (!diag) {
        #pragma unroll
        for (int i = 0; i < 8; i++) {
            ca[i] += __shfl_xor_sync(0xffffffffu, ca[i], 4);
            ca[i] += __shfl_xor_sync(0xffffffffu, ca[i], 8);
            ca[i] += __shfl_xor_sync(0xffffffffu, ca[i], 16);
        }
        if (lane < 4) {
            #pragma unroll
            for (int i = 0; i < 8; i++) {
                int cl = wn * 32 + (i >> 1) * 8 + 2 * t + (i & 1);
                cred[cl * 4 + wm] = ca[i];
            }
        }
    }
}

// ---------------- Kernel: fused normalize + grid barrier + symmetric GEMM ----------------
__global__ void __launch_bounds__(512, 1) simclr_fused(const float* __restrict__ feats) {
    extern __shared__ unsigned char smem_raw[];
    const uint32_t sbase = smem_u32(smem_raw);
    const int tid = threadIdx.x;
    const int warp = tid >> 5, lane = tid & 31;
    const int c = blockIdx.x;

    // ---- phase 1: normalize + prescale (strided rows) ----
    {
        int base_row = 110 * c + min(c, 104);
        int cnt = (c < 104) ? 111 : 110;
        for (int r = warp; r < cnt; r += 16) {
            int row = base_row + r;
            const float4* src = reinterpret_cast<const float4*>(feats + (size_t)row * DIM);
            float4 v = src[lane];
            float ss = v.x*v.x + v.y*v.y + v.z*v.z + v.w*v.w;
            #pragma unroll
            for (int o = 16; o; o >>= 1) ss += __shfl_xor_sync(0xffffffffu, ss, o);
            float inv = SQRT_SCALE2 / fmaxf(sqrtf(ss), 1e-8f);
            __nv_bfloat162 p0 = __floats2bfloat162_rn(v.x*inv, v.y*inv);
            __nv_bfloat162 p1 = __floats2bfloat162_rn(v.z*inv, v.w*inv);
            uint2 w;
            w.x = *reinterpret_cast<uint32_t*>(&p0);
            w.y = *reinterpret_cast<uint32_t*>(&p1);
            reinterpret_cast<uint2*>(g_fn + (size_t)row * DIM)[lane] = w;
        }
    }
    // zero rowacc + red/cred while waiting
    #pragma unroll
    for (int i = 0; i < 8; i++)
        reinterpret_cast<float4*>(smem_raw + SM_ROWACC)[tid + 512 * i] =
            make_float4(0.f, 0.f, 0.f, 0.f);
    reinterpret_cast<float4*>(smem_raw + SM_RED)[tid] = make_float4(0.f, 0.f, 0.f, 0.f);

    // grid barrier (monotonic counter — safe across graph replays)
    __threadfence();
    __syncthreads();
    if (tid == 0) {
        unsigned int old = atomicAdd(&g_ctr0, 1u);
        unsigned int target = old - (old % GRID) + GRID;
        while (atomicAdd(&g_ctr0, 0u) < target) __nanosleep(64);
    }
    __syncthreads();

    // ---- phase 2: unit loop ----
    int u = 55 * c + min(c, 116);
    const int u_end = u + ((c < 116) ? 56 : 55);
    int bi, bj;
    decode_unit(u, bi, bj);
    int abuf = 0, bbuf = 0;
    load_tile(sbase, g_fn + (size_t)bi * 16384, tid);
    load_tile(sbase + 2 * TILE_BYTES, g_fn + (size_t)bj * 16384, tid);
    cp_commit();

    float c0[32], c1[32];
    int nbi, nbj;
    bool has_next = (u + 1 < u_end);
    nbj = bj + 1; nbi = bi; if (nbj == 128) { nbi = bi + 1; nbj = nbi; }
    bool loadA = has_next && (nbi != bi);
    step<false>(sbase, smem_raw, abuf, bbuf, has_next, loadA, nbi, nbj,
                false, 0, 0, true, 0, c0, c1);
    int pbi = bi, pbj = bj;  bool pdiag = (pbi == pbj);
    int ppbi = bi, ppbj = bi; bool ppdiag = true;       // dummy (adds zeros)
    int wp = 0;
    u++; bbuf ^= 1; if (loadA) abuf ^= 1; bi = nbi; bj = nbj;

    bool lastInC1 = false;
    #pragma unroll 1
    while (u + 1 < u_end) {
        // first of pair: cc=c1, cp=c0
        nbj = bj + 1; nbi = bi; if (nbj == 128) { nbi = bi + 1; nbj = nbi; }
        loadA = (nbi != bi);
        step<true>(sbase, smem_raw, abuf, bbuf, true, loadA, nbi, nbj,
                   pdiag, ppbi, ppbj, ppdiag, wp, c1, c0);
        ppbi = pbi; ppbj = pbj; ppdiag = pdiag;
        pbi = bi; pbj = bj; pdiag = (pbi == pbj);
        wp ^= 1; u++; bbuf ^= 1; if (loadA) abuf ^= 1; bi = nbi; bj = nbj;

        // second of pair: cc=c0, cp=c1
        has_next = (u + 1 < u_end);
        nbj = bj + 1; nbi = bi; if (nbj == 128) { nbi = bi + 1; nbj = nbi; }
        loadA = has_next && (nbi != bi);
        step<true>(sbase, smem_raw, abuf, bbuf, has_next, loadA, nbi, nbj,
                   pdiag, ppbi, ppbj, ppdiag, wp, c0, c1);
        ppbi = pbi; ppbj = pbj; ppdiag = pdiag;
        pbi = bi; pbj = bj; pdiag = (pbi == pbj);
        wp ^= 1; u++; bbuf ^= 1; if (loadA) abuf ^= 1; bi = nbi; bj = nbj;
    }
    if (u < u_end) {          // one leftover unit: cc=c1, cp=c0
        step<true>(sbase, smem_raw, abuf, bbuf, false, false, bi, bj,
                   pdiag, ppbi, ppbj, ppdiag, wp, c1, c0);
        ppbi = pbi; ppbj = pbj; ppdiag = pdiag;
        pbi = bi; pbj = bj; pdiag = (pbi == pbj);
        wp ^= 1;
        lastInC1 = true;
    }

    // ---- tail: flush last unit's epilogue + two lagged accumulates ----
    if (lastInC1) tail_flush(smem_raw, c1, pdiag, wp);
    else          tail_flush(smem_raw, c0, pdiag, wp);
    __syncthreads();
    {
        float* rowacc = (float*)(smem_raw + SM_ROWACC);
        if (tid < 128) {
            const float4* r0 = (const float4*)(smem_raw + SM_RED + (wp ^ 1) * 2048);
            float4 v0 = r0[tid];
            rowacc[ppbi * 128 + tid] += (v0.x + v0.y) + (v0.z + v0.w);
            const float4* r1 = (const float4*)(smem_raw + SM_RED + wp * 2048);
            float4 v1 = r1[tid];
            rowacc[pbi * 128 + tid] += (v1.x + v1.y) + (v1.z + v1.w);
        } else if (tid < 256) {
            int c2 = tid - 128;
            if (!ppdiag) {
                const float4* q0 = (const float4*)(smem_raw + SM_CRED + (wp ^ 1) * 2048);
                float4 v0 = q0[c2];
                rowacc[ppbj * 128 + c2] += (v0.x + v0.y) + (v0.z + v0.w);
            }
            if (!pdiag) {
                const float4* q1 = (const float4*)(smem_raw + SM_CRED + wp * 2048);
                float4 v1 = q1[c2];
                rowacc[pbj * 128 + c2] += (v1.x + v1.y) + (v1.z + v1.w);
            }
        }
    }
    __syncthreads();
    float* dst = g_partial + (size_t)c * N_ROWS;
    #pragma unroll
    for (int i = 0; i < 8; i++) {
        int idx = tid + 512 * i;
        reinterpret_cast<float4*>(dst)[idx] =
            reinterpret_cast<const float4*>(smem_raw + SM_ROWACC)[idx];
    }
}

// ---------------- Kernel: row sums + log, fused final mean ----------------
__global__ void __launch_bounds__(256) lse_final(float* __restrict__ out) {
    __shared__ float s[256];
    __shared__ int amLast;
    int row = blockIdx.x * 256 + threadIdx.x;
    float s0 = 0.f, s1 = 0.f, s2 = 0.f, s3 = 0.f;
    #pragma unroll 4
    for (int c = 0; c < GRID; c += 4) {
        s0 += g_partial[(size_t)c * N_ROWS + row];
        s1 += g_partial[(size_t)(c + 1) * N_ROWS + row];
        s2 += g_partial[(size_t)(c + 2) * N_ROWS + row];
        s3 += g_partial[(size_t)(c + 3) * N_ROWS + row];
    }
    s[threadIdx.x] = logf((s0 + s1) + (s2 + s3));
    __syncthreads();
    #pragma unroll
    for (int o = 128; o; o >>= 1) {
        if (threadIdx.x < o) s[threadIdx.x] += s[threadIdx.x + o];
        __syncthreads();
    }
    if (threadIdx.x == 0) g_blocksum[blockIdx.x] = s[0];
    __threadfence();
    if (threadIdx.x == 0) {
        unsigned int t2 = atomicAdd(&g_ctr2, 1u);
        amLast = ((t2 % 64u) == 63u) ? 1 : 0;
    }
    __syncthreads();
    if (amLast) {
        if (threadIdx.x < 64) {
            const volatile float* bs = g_blocksum;   // .cv loads bypass L1
            float v = bs[threadIdx.x];
            #pragma unroll
            for (int o = 16; o; o >>= 1) v += __shfl_xor_sync(0xffffffffu, v, o);
            __shared__ float w2[2];
            if ((threadIdx.x & 31) == 0) w2[threadIdx.x >> 5] = v;
            __syncwarp();
            __syncthreads();
            if (threadIdx.x == 0)
                out[0] = (w2[0] + w2[1]) * (1.0f / 16384.0f) - 1.2857142857142857e-13f;
        } else {
            __syncthreads();
        }
    }
}

extern "C" void kernel_launch(void* const* d_in, const int* in_sizes, int n_in,
                              void* d_out, int out_size) {
    const float* feats = (const float*)d_in[0];
    float* out = (float*)d_out;

    cudaFuncSetAttribute(simclr_fused,
                         cudaFuncAttributeMaxDynamicSharedMemorySize, SMEM_TOTAL);

    simclr_fused<<<GRID, 512, SMEM_TOTAL>>>(feats);
    lse_final<<<64, 256>>>(out);
}

// round 7
// speedup vs baseline: 1.2065x; 1.0082x over previous
#include <cuda_runtime.h>
#include <cuda_bf16.h>
#include <cstdint>

#define N_ROWS 16384
#define DIM 128
#define SQRT_SCALE2 4.5398160f   // sqrt(log2(e)/0.07)
#define GRID 148
#define NUNITS 8256              // 128*129/2 upper-triangular block pairs

__device__ __nv_bfloat16 g_fn[N_ROWS * DIM];
__device__ float g_partial[GRID * N_ROWS];
__device__ float g_blocksum[256];
__device__ unsigned int g_ctr0;   // grid barrier (normalize -> gemm), monotonic
__device__ unsigned int g_ctr2;   // lse -> final fusion counter, monotonic

#define TILE_BYTES 34816                 // 128 rows x 272B (136 bf16 padded)
#define SM_ROWACC  (4 * TILE_BYTES)      // 16384 floats (64KB)
#define SM_RED     (SM_ROWACC + 65536)   // 2 parities x 128x4 floats
#define SM_CRED    (SM_RED + 4096)       // 2 parities x 128x4 floats
#define SMEM_TOTAL (SM_CRED + 4096)      // 212992

__device__ __forceinline__ float fast_ex2(float x) {
    float y; asm("ex2.approx.ftz.f32 %0, %1;" : "=f"(y) : "f"(x)); return y;
}
__device__ __forceinline__ uint32_t smem_u32(const void* p) {
    uint32_t a;
    asm("{ .reg .u64 t; cvta.to.shared.u64 t, %1; cvt.u32.u64 %0, t; }" : "=r"(a) : "l"(p));
    return a;
}
__device__ __forceinline__ void cp16(uint32_t dst, const void* src) {
    asm volatile("cp.async.cg.shared.global [%0], [%1], 16;" :: "r"(dst), "l"(src));
}
__device__ __forceinline__ void cp_commit()   { asm volatile("cp.async.commit_group;"); }
__device__ __forceinline__ void cp_wait_all() { asm volatile("cp.async.wait_group 0;" ::: "memory"); }

__device__ __forceinline__ void ldsm4(uint32_t r[4], uint32_t addr) {
    asm volatile("ldmatrix.sync.aligned.m8n8.x4.shared.b16 {%0,%1,%2,%3}, [%4];"
                 : "=r"(r[0]), "=r"(r[1]), "=r"(r[2]), "=r"(r[3]) : "r"(addr));
}
__device__ __forceinline__ void mma16816(float* c, const uint32_t a[4], const uint32_t* b) {
    asm volatile(
      "mma.sync.aligned.m16n8k16.row.col.f32.bf16.bf16.f32 "
      "{%0,%1,%2,%3}, {%4,%5,%6,%7}, {%8,%9}, {%0,%1,%2,%3};\n"
      : "+f"(c[0]), "+f"(c[1]), "+f"(c[2]), "+f"(c[3])
      : "r"(a[0]), "r"(a[1]), "r"(a[2]), "r"(a[3]), "r"(b[0]), "r"(b[1]));
}

__device__ __forceinline__ int tri_base(int bi) { return bi * 128 - (bi * (bi - 1)) / 2; }
__device__ __forceinline__ void decode_unit(int u, int& bi, int& bj) {
    int b = (int)((257.0f - sqrtf(66049.0f - 8.0f * (float)u)) * 0.5f);
    while (tri_base(b + 1) <= u) b++;
    while (tri_base(b) > u) b--;
    bi = b;
    bj = b + (u - tri_base(b));
}

__device__ __forceinline__ void load_tile(uint32_t dstbase, const __nv_bfloat16* src, int tid) {
    #pragma unroll
    for (int i = 0; i < 4; i++) {
        int c = tid + 512 * i;
        int row = c >> 4, q = c & 15;
        cp16(dstbase + (uint32_t)(row * 17 + q) * 16, src + row * DIM + q * 8);
    }
}

// ---- MMA k-loop with interleaved ex2 epilogue of previous unit ----
// racc: persistent per-thread row partials (flushed only on run change).
// ca:   column partials for this (previous) unit, skipped for diagonal tiles.
template<bool EPI, bool PDIAG>
__device__ __forceinline__ void kloop(uint32_t abase, uint32_t bbase,
                                      float (&cc)[32], float (&cp)[32],
                                      float (&racc)[4], float (&ca)[8]) {
    const int lane = threadIdx.x & 31, warp = threadIdx.x >> 5;
    const int wm = warp >> 2, wn = warp & 3;
    const int g = lane >> 2, t = lane & 3;
    uint32_t aA0, aB0;
    {
        int rowA = lane & 15, koffA = (lane >> 4) * 16;
        aA0 = abase + (uint32_t)((wm * 32 + rowA) * 272 + koffA);
        int rowB = ((lane & 16) >> 1) + (lane & 7), koffB = ((lane >> 3) & 1) * 16;
        aB0 = bbase + (uint32_t)((wn * 32 + rowB) * 272 + koffB);
    }
    const int epi_r0 = wm * 32 + g, epi_c0 = wn * 32 + 2 * t;

    #pragma unroll
    for (int e = 0; e < 32; e++) cc[e] = 0.f;
    #pragma unroll
    for (int ks = 0; ks < 8; ks++) {
        uint32_t a0[4], a1[4], b0[4], b1[4];
        ldsm4(a0, aA0 + ks * 32);
        ldsm4(a1, aA0 + 16 * 272 + ks * 32);
        ldsm4(b0, aB0 + ks * 32);
        ldsm4(b1, aB0 + 16 * 272 + ks * 32);
        mma16816(&cc[0],  a0, b0 + 0); mma16816(&cc[4],  a0, b0 + 2);
        mma16816(&cc[8],  a0, b1 + 0); mma16816(&cc[12], a0, b1 + 2);
        mma16816(&cc[16], a1, b0 + 0); mma16816(&cc[20], a1, b0 + 2);
        mma16816(&cc[24], a1, b1 + 0); mma16816(&cc[28], a1, b1 + 2);
        if (EPI) {
            #pragma unroll
            for (int i = 0; i < 4; i++) {
                const int e = ks * 4 + i;
                const int mt = e >> 4, nt = (e >> 2) & 3, comp = e & 3;
                float ex = fast_ex2(cp[e]);
                if (PDIAG) {
                    int r  = epi_r0 + mt * 16 + (comp & 2) * 4;
                    int cl = epi_c0 + nt * 8 + (comp & 1);
                    if (r == cl) ex = 1.f;             // masked diag: exp==1
                    racc[mt * 2 + (comp >> 1)] += ex;  // diag: rows only
                } else {
                    racc[mt * 2 + (comp >> 1)] += ex;
                    ca[nt * 2 + (comp & 1)] += ex;
                }
            }
        }
    }
}

__device__ __forceinline__ void flush_rows(unsigned char* smem_raw, float (&racc)[4], int wp) {
    const int lane = threadIdx.x & 31, warp = threadIdx.x >> 5;
    const int g = lane >> 2, t = lane & 3;
    const int wm = warp >> 2, wn = warp & 3;
    float rr[4];
    #pragma unroll
    for (int i = 0; i < 4; i++) {
        rr[i] = racc[i]; racc[i] = 0.f;
        rr[i] += __shfl_xor_sync(0xffffffffu, rr[i], 1);
        rr[i] += __shfl_xor_sync(0xffffffffu, rr[i], 2);
    }
    if (t == 0) {
        float* red = (float*)(smem_raw + SM_RED + wp * 2048);
        #pragma unroll
        for (int i = 0; i < 4; i++) {
            int r = wm * 32 + (i >> 1) * 16 + g + (i & 1) * 8;
            red[r * 4 + wn] = rr[i];
        }
    }
}

__device__ __forceinline__ void flush_cols(unsigned char* smem_raw, float (&ca)[8], int wp) {
    const int lane = threadIdx.x & 31, warp = threadIdx.x >> 5;
    const int t = lane & 3;
    const int wm = warp >> 2, wn = warp & 3;
    #pragma unroll
    for (int i = 0; i < 8; i++) {
        ca[i] += __shfl_xor_sync(0xffffffffu, ca[i], 4);
        ca[i] += __shfl_xor_sync(0xffffffffu, ca[i], 8);
        ca[i] += __shfl_xor_sync(0xffffffffu, ca[i], 16);
    }
    if (lane < 4) {
        float* cred = (float*)(smem_raw + SM_CRED + wp * 2048);
        #pragma unroll
        for (int i = 0; i < 8; i++) {
            int cl = wn * 32 + (i >> 1) * 8 + 2 * t + (i & 1);
            cred[cl * 4 + wm] = ca[i];
        }
    }
}

// One pipeline step: barrier, lagged accumulates (parity wp^1), prefetch u+1,
// MMA of current unit into cc with interleaved ex2 of previous into racc/ca,
// then col flush of the previous unit to cred[wp].
template<bool EPI>
__device__ __forceinline__ void do_step(uint32_t sbase, unsigned char* smem_raw, int tid,
                                        int abuf, int bbuf,
                                        bool has_next, bool loadA_next, int nbi, int nbj,
                                        bool pdiag, int wp, int lag_row, int lag_col,
                                        float (&cc)[32], float (&cp)[32], float (&racc)[4]) {
    cp_wait_all();
    __syncthreads();

    float* rowacc = (float*)(smem_raw + SM_ROWACC);
    if (tid < 128) {
        if (lag_row >= 0) {
            const float4* rp = (const float4*)(smem_raw + SM_RED + (wp ^ 1) * 2048);
            float4 v = rp[tid];
            rowacc[lag_row * 128 + tid] += (v.x + v.y) + (v.z + v.w);
        }
    } else if (tid < 256) {
        if (lag_col >= 0) {
            const float4* cq = (const float4*)(smem_raw + SM_CRED + (wp ^ 1) * 2048);
            float4 v = cq[tid - 128];
            rowacc[lag_col * 128 + (tid - 128)] += (v.x + v.y) + (v.z + v.w);
        }
    }

    if (has_next) {
        load_tile(sbase + (uint32_t)(2 + (bbuf ^ 1)) * TILE_BYTES,
                  g_fn + (size_t)nbj * 16384, tid);
        if (loadA_next)
            load_tile(sbase + (uint32_t)(abuf ^ 1) * TILE_BYTES,
                      g_fn + (size_t)nbi * 16384, tid);
        cp_commit();
    }

    const uint32_t abase = sbase + (uint32_t)abuf * TILE_BYTES;
    const uint32_t bbase = sbase + (uint32_t)(2 + bbuf) * TILE_BYTES;
    float ca[8] = {0.f, 0.f, 0.f, 0.f, 0.f, 0.f, 0.f, 0.f};
    if (EPI && pdiag)      kloop<true, true >(abase, bbase, cc, cp, racc, ca);
    else if (EPI)          kloop<true, false>(abase, bbase, cc, cp, racc, ca);
    else                   kloop<false, false>(abase, bbase, cc, cp, racc, ca);
    if (EPI && !pdiag) flush_cols(smem_raw, ca, wp);
}

__device__ __forceinline__ void tail_epi(unsigned char* smem_raw, float (&cp)[32],
                                         float (&racc)[4], bool pdiag, int wp) {
    const int lane = threadIdx.x & 31, warp = threadIdx.x >> 5;
    const int g = lane >> 2, t = lane & 3;
    const int wm = warp >> 2, wn = warp & 3;
    const int epi_r0 = wm * 32 + g, epi_c0 = wn * 32 + 2 * t;
    float ca[8] = {0.f, 0.f, 0.f, 0.f, 0.f, 0.f, 0.f, 0.f};
    #pragma unroll
    for (int e = 0; e < 32; e++) {
        const int mt = e >> 4, nt = (e >> 2) & 3, comp = e & 3;
        float ex = fast_ex2(cp[e]);
        int r  = epi_r0 + mt * 16 + (comp & 2) * 4;
        int cl = epi_c0 + nt * 8 + (comp & 1);
        if (pdiag && r == cl) ex = 1.f;
        racc[mt * 2 + (comp >> 1)] += ex;
        ca[nt * 2 + (comp & 1)] += ex;
    }
    flush_rows(smem_raw, racc, wp);
    if (!pdiag) flush_cols(smem_raw, ca, wp);
}

// ---------------- Kernel: fused normalize + grid barrier + symmetric GEMM ----------------
__global__ void __launch_bounds__(512, 1) simclr_fused(const float* __restrict__ feats) {
    extern __shared__ unsigned char smem_raw[];
    const uint32_t sbase = smem_u32(smem_raw);
    const int tid = threadIdx.x;
    const int warp = tid >> 5, lane = tid & 31;
    const int c = blockIdx.x;

    // ---- phase 1: normalize + prescale (2 rows in flight per warp) ----
    {
        int base_row = 110 * c + min(c, 104);
        int cnt = (c < 104) ? 111 : 110;
        for (int r = warp * 2; r < cnt; r += 32) {
            int row0 = base_row + r;
            bool has2 = (r + 1 < cnt);
            int row1 = has2 ? (row0 + 1) : row0;
            float4 v0 = reinterpret_cast<const float4*>(feats + (size_t)row0 * DIM)[lane];
            float4 v1 = reinterpret_cast<const float4*>(feats + (size_t)row1 * DIM)[lane];
            float s0 = v0.x*v0.x + v0.y*v0.y + v0.z*v0.z + v0.w*v0.w;
            float s1 = v1.x*v1.x + v1.y*v1.y + v1.z*v1.z + v1.w*v1.w;
            #pragma unroll
            for (int o = 16; o; o >>= 1) {
                s0 += __shfl_xor_sync(0xffffffffu, s0, o);
                s1 += __shfl_xor_sync(0xffffffffu, s1, o);
            }
            float i0 = SQRT_SCALE2 / fmaxf(sqrtf(s0), 1e-8f);
            float i1 = SQRT_SCALE2 / fmaxf(sqrtf(s1), 1e-8f);
            __nv_bfloat162 p0 = __floats2bfloat162_rn(v0.x*i0, v0.y*i0);
            __nv_bfloat162 p1 = __floats2bfloat162_rn(v0.z*i0, v0.w*i0);
            uint2 w0;
            w0.x = *reinterpret_cast<uint32_t*>(&p0);
            w0.y = *reinterpret_cast<uint32_t*>(&p1);
            reinterpret_cast<uint2*>(g_fn + (size_t)row0 * DIM)[lane] = w0;
            if (has2) {
                __nv_bfloat162 q0 = __floats2bfloat162_rn(v1.x*i1, v1.y*i1);
                __nv_bfloat162 q1 = __floats2bfloat162_rn(v1.z*i1, v1.w*i1);
                uint2 w1;
                w1.x = *reinterpret_cast<uint32_t*>(&q0);
                w1.y = *reinterpret_cast<uint32_t*>(&q1);
                reinterpret_cast<uint2*>(g_fn + (size_t)row1 * DIM)[lane] = w1;
            }
        }
    }
    // zero rowacc while waiting
    #pragma unroll
    for (int i = 0; i < 8; i++)
        reinterpret_cast<float4*>(smem_raw + SM_ROWACC)[tid + 512 * i] =
            make_float4(0.f, 0.f, 0.f, 0.f);

    // grid barrier (monotonic counter — safe across graph replays)
    __threadfence();
    __syncthreads();
    if (tid == 0) {
        unsigned int old = atomicAdd(&g_ctr0, 1u);
        unsigned int target = old - (old % GRID) + GRID;
        while (atomicAdd(&g_ctr0, 0u) < target) __nanosleep(64);
    }
    __syncthreads();

    // ---- phase 2: unit loop (contiguous row-major triangular walk) ----
    const int u0 = 55 * c + min(c, 116);
    const int count = (c < 116) ? 56 : 55;

    int bi, bj;
    decode_unit(u0, bi, bj);
    int abuf = 0, bbuf = 0;
    load_tile(sbase, g_fn + (size_t)bi * 16384, tid);
    load_tile(sbase + 2 * TILE_BYTES, g_fn + (size_t)bj * 16384, tid);
    cp_commit();

    float cA[32], cB[32], racc[4] = {0.f, 0.f, 0.f, 0.f};

    // step 0: MMA(u0) into cA, no epilogue
    int nbi = bi, nbj = bj + 1;
    if (nbj == 128) { nbi = bi + 1; nbj = nbi; }
    bool has_next = (count > 1);
    bool loadA = has_next && (nbi != bi);
    do_step<false>(sbase, smem_raw, tid, abuf, bbuf, has_next, loadA, nbi, nbj,
                   false, 0, -1, -1, cA, cB, racc);
    int pbi = bi, pbj = bj;
    bool pdiag = (bi == bj);
    bbuf ^= 1; if (loadA) abuf ^= 1;
    bi = nbi; bj = nbj;

    int lag_row = -1, lag_col = -1;
    int wp = 1;
    #pragma unroll 1
    for (int s = 1; s < count; s++) {
        nbj = bj + 1; nbi = bi;
        if (nbj == 128) { nbi = bi + 1; nbj = nbi; }
        has_next = (s + 1 < count);
        loadA = has_next && (nbi != bi);
        const bool rowflush = (bi != pbi);   // previous unit ended its run

        if (s & 1) do_step<true>(sbase, smem_raw, tid, abuf, bbuf, has_next, loadA,
                                 nbi, nbj, pdiag, wp, lag_row, lag_col, cB, cA, racc);
        else       do_step<true>(sbase, smem_raw, tid, abuf, bbuf, has_next, loadA,
                                 nbi, nbj, pdiag, wp, lag_row, lag_col, cA, cB, racc);
        if (rowflush) flush_rows(smem_raw, racc, wp);
        lag_row = rowflush ? pbi : -1;
        lag_col = pdiag ? -1 : pbj;
        pbi = bi; pbj = bj; pdiag = (bi == bj);
        bbuf ^= 1; if (loadA) abuf ^= 1;
        bi = nbi; bj = nbj;
        wp ^= 1;
    }

    // ---- tail ----
    __syncthreads();   // last loop step's STS (parity wp^1) visible
    {
        float* rowacc = (float*)(smem_raw + SM_ROWACC);
        if (tid < 128 && lag_row >= 0) {
            const float4* rp = (const float4*)(smem_raw + SM_RED + (wp ^ 1) * 2048);
            float4 v = rp[tid];
            rowacc[lag_row * 128 + tid] += (v.x + v.y) + (v.z + v.w);
        } else if (tid >= 128 && tid < 256 && lag_col >= 0) {
            const float4* cq = (const float4*)(smem_raw + SM_CRED + (wp ^ 1) * 2048);
            float4 v = cq[tid - 128];
            rowacc[lag_col * 128 + (tid - 128)] += (v.x + v.y) + (v.z + v.w);
        }
    }
    // epilogue of final unit (always closes a run) -> red/cred[wp]
    if ((count - 1) & 1) tail_epi(smem_raw, cB, racc, pdiag, wp);
    else                 tail_epi(smem_raw, cA, racc, pdiag, wp);
    __syncthreads();
    {
        float* rowacc = (float*)(smem_raw + SM_ROWACC);
        if (tid < 128) {
            const float4* rp = (const float4*)(smem_raw + SM_RED + wp * 2048);
            float4 v = rp[tid];
            rowacc[pbi * 128 + tid] += (v.x + v.y) + (v.z + v.w);
        } else if (tid < 256 && !pdiag) {
            const float4* cq = (const float4*)(smem_raw + SM_CRED + wp * 2048);
            float4 v = cq[tid - 128];
            rowacc[pbj * 128 + (tid - 128)] += (v.x + v.y) + (v.z + v.w);
        }
    }
    __syncthreads();
    float* dst = g_partial + (size_t)c * N_ROWS;
    #pragma unroll
    for (int i = 0; i < 8; i++) {
        int idx = tid + 512 * i;
        reinterpret_cast<float4*>(dst)[idx] =
            reinterpret_cast<const float4*>(smem_raw + SM_ROWACC)[idx];
    }
}

// ---------------- Kernel: parallel row sums + log + fused final mean ----------------
// 256 blocks x 256 threads; each block owns 64 rows; the 148 partials are split
// 4 ways (148 = 4*37) across tid>>6, fully unrolled for MLP.
__global__ void __launch_bounds__(256) lse_final(float* __restrict__ out) {
    __shared__ float s[256];
    __shared__ int amLast;
    const int tid = threadIdx.x;
    const int row = blockIdx.x * 64 + (tid & 63);
    const int cbeg = (tid >> 6) * 37;
    float acc = 0.f;
    #pragma unroll
    for (int k = 0; k < 37; k++)
        acc += __ldcg(&g_partial[(size_t)(cbeg + k) * N_ROWS + row]);
    s[tid] = acc;
    __syncthreads();
    if (tid < 64) {
        float v = (s[tid] + s[tid + 64]) + (s[tid + 128] + s[tid + 192]);
        float l = logf(v);
        #pragma unroll
        for (int o = 16; o; o >>= 1) l += __shfl_xor_sync(0xffffffffu, l, o);
        if ((tid & 31) == 0) s[tid >> 5] = l;
    }
    __syncthreads();
    if (tid == 0) g_blocksum[blockIdx.x] = s[0] + s[1];
    __threadfence();
    if (tid == 0) {
        unsigned int t2 = atomicAdd(&g_ctr2, 1u);
        amLast = ((t2 % 256u) == 255u) ? 1 : 0;
    }
    __syncthreads();
    if (amLast) {
        const volatile float* bs = g_blocksum;
        float v = bs[tid];
        #pragma unroll
        for (int o = 16; o; o >>= 1) v += __shfl_xor_sync(0xffffffffu, v, o);
        if ((tid & 31) == 0) s[tid >> 5] = v;
        __syncthreads();
        if (tid == 0) {
            float tot = 0.f;
            #pragma unroll
            for (int i = 0; i < 8; i++) tot += s[i];
            out[0] = tot * (1.0f / 16384.0f) - 1.2857142857142857e-13f;
        }
    }
}

extern "C" void kernel_launch(void* const* d_in, const int* in_sizes, int n_in,
                              void* d_out, int out_size) {
    const float* feats = (const float*)d_in[0];
    float* out = (float*)d_out;

    cudaFuncSetAttribute(simclr_fused,
                         cudaFuncAttributeMaxDynamicSharedMemorySize, SMEM_TOTAL);

    simclr_fused<<<GRID, 512, SMEM_TOTAL>>>(feats);
    lse_final<<<256, 256>>>(out);
}